// round 13
// baseline (speedup 1.0000x reference)
#include <cuda_runtime.h>
#include <cuda_fp16.h>
#include <cstdint>

// Problem constants
#define BATCH 8
#define SEQ   1024
#define CD    1024
#define NH    16
#define HD    64
#define MTOK  (BATCH * SEQ)      // 8192 tokens
#define NQKV  (3 * CD)           // 3072

// Scratch (no allocations allowed -> __device__ globals)
__device__ __half g_xh[MTOK * CD];
__device__ __half g_wah[NQKV * CD];
__device__ __half g_wph[CD * CD];
__device__ __half g_qkvh[MTOK * NQKV];
__device__ __half g_yh[MTOK * CD];

// ---------------------------------------------------------------------------
// PTX helpers (portable sm_80+ tensor path: cp.async + ldmatrix + mma.sync)
// ---------------------------------------------------------------------------
__device__ __forceinline__ uint32_t smem_u32(const void* p) {
    return (uint32_t)__cvta_generic_to_shared(p);
}
__device__ __forceinline__ void cp16(uint32_t dst_smem, const void* src) {
    asm volatile("cp.async.cg.shared.global [%0], [%1], 16;"
                 :: "r"(dst_smem), "l"(__cvta_generic_to_global(src)) : "memory");
}
__device__ __forceinline__ void ldsm4(uint32_t* r, uint32_t addr) {
    asm volatile("ldmatrix.sync.aligned.m8n8.x4.shared.b16 {%0,%1,%2,%3}, [%4];"
                 : "=r"(r[0]), "=r"(r[1]), "=r"(r[2]), "=r"(r[3]) : "r"(addr));
}
__device__ __forceinline__ void ldsm4t(uint32_t* r, uint32_t addr) {
    asm volatile("ldmatrix.sync.aligned.m8n8.x4.trans.shared.b16 {%0,%1,%2,%3}, [%4];"
                 : "=r"(r[0]), "=r"(r[1]), "=r"(r[2]), "=r"(r[3]) : "r"(addr));
}
// fp32-accumulate MMA (used by attention)
__device__ __forceinline__ void mma16816(float* d, const uint32_t* a,
                                         uint32_t b0, uint32_t b1) {
    asm volatile(
        "mma.sync.aligned.m16n8k16.row.col.f32.f16.f16.f32 "
        "{%0,%1,%2,%3}, {%4,%5,%6,%7}, {%8,%9}, {%0,%1,%2,%3};"
        : "+f"(d[0]), "+f"(d[1]), "+f"(d[2]), "+f"(d[3])
        : "r"(a[0]), "r"(a[1]), "r"(a[2]), "r"(a[3]), "r"(b0), "r"(b1));
}
// fp16-accumulate MMA (GEMM fast path; promoted to fp32 per-MMA)
__device__ __forceinline__ void mma16816h(uint32_t& d0, uint32_t& d1,
                                          const uint32_t* a,
                                          uint32_t b0, uint32_t b1) {
    asm volatile(
        "mma.sync.aligned.m16n8k16.row.col.f16.f16.f16.f16 "
        "{%0,%1}, {%2,%3,%4,%5}, {%6,%7}, {%0,%1};"
        : "+r"(d0), "+r"(d1)
        : "r"(a[0]), "r"(a[1]), "r"(a[2]), "r"(a[3]), "r"(b0), "r"(b1));
}
__device__ __forceinline__ uint32_t pack2(float a, float b) {
    __half2 h = __floats2half2_rn(a, b);
    return *(uint32_t*)&h;
}

// 128B-row swizzle: 16B chunk ch (0..7) of row r
__device__ __forceinline__ uint32_t swa(uint32_t r, uint32_t ch) {
    return r * 128u + (((ch) ^ (r & 7u)) << 4);
}

// ---------------------------------------------------------------------------
// fused fp32 -> fp16 convert for 3 tensors in one launch
// ---------------------------------------------------------------------------
__global__ __launch_bounds__(256)
void cvt3_f16(const float* __restrict__ a, __half* __restrict__ ah, int na,
              const float* __restrict__ b, __half* __restrict__ bh, int nb,
              const float* __restrict__ c, __half* __restrict__ ch, int nc)
{
    int i = (blockIdx.x * blockDim.x + threadIdx.x) * 4;
    const float* src;
    __half* dst;
    if (i < na)            { src = a + i;            dst = ah + i; }
    else if (i < na + nb)  { src = b + (i - na);     dst = bh + (i - na); }
    else if (i < na + nb + nc) { src = c + (i - na - nb); dst = ch + (i - na - nb); }
    else return;
    float4 v = *(const float4*)src;
    *(uint32_t*)dst       = pack2(v.x, v.y);
    *(uint32_t*)(dst + 2) = pack2(v.z, v.w);
}

// ---------------------------------------------------------------------------
// fp16 mma.sync GEMM: C[m,n] = sum_k A[m,k] * B[n,k]  (+bias)
// 128x256 CTA tile, 8 warps, each 64x64, BK=64, 3-stage cp.async pipe.
// fp16-accumulate HMMA, promoted per-MMA into fp32 accumulators.
// ---------------------------------------------------------------------------
#define A_ST   16384                    // 128 rows x 128B
#define B_ST   32768                    // 256 rows x 128B
#define STAGE_BYTES (A_ST + B_ST)       // 48 KB
#define NSTAGE 3
#define GEMM_SMEM (NSTAGE * STAGE_BYTES)  // 144 KB

template <bool BIAS, bool OUTH>
__global__ __launch_bounds__(256, 1)
void gemm_f16(const __half* __restrict__ A, const __half* __restrict__ B,
              const float* __restrict__ bias, float* __restrict__ C,
              __half* __restrict__ Ch, int M, int N, int K)
{
    extern __shared__ char smem[];
    const uint32_t sb = smem_u32(smem);
    const int tid = threadIdx.x;
    const int wid = tid >> 5, l = tid & 31;
    const int m0 = blockIdx.y * 128, n0 = blockIdx.x * 256;
    const int NCH = K >> 6;            // BK=64

    // loader: A = 128 rows, 2 thr/row (4 cp16 each); B = 256 rows, 1 thr/row
    const int alr = tid >> 1, alc = (tid & 1) * 4;
    const __half* agp = A + (size_t)(m0 + alr) * K + alc * 8;
    const __half* bgp = B + (size_t)(n0 + tid) * K;

    auto load_chunk = [&](int c) {
        const uint32_t stage = sb + (uint32_t)(c % NSTAGE) * STAGE_BYTES;
        const int k0 = c << 6;
#pragma unroll
        for (int ch = 0; ch < 4; ch++)
            cp16(stage + swa(alr, alc + ch), agp + k0 + ch * 8);
#pragma unroll
        for (int ch = 0; ch < 8; ch++)
            cp16(stage + A_ST + swa(tid, ch), bgp + k0 + ch * 8);
        asm volatile("cp.async.commit_group;" ::: "memory");
    };

    // warp tile 64x64: wm in {0,1} (m), wn in {0..3} (n)
    const int wm = wid & 1, wn = wid >> 1;

    const uint32_t arow = wm * 64 + (l & 15);
    const uint32_t ach  = l >> 4;
    const uint32_t brow = wn * 64 + (l & 7) + ((l >> 4) << 3);
    const uint32_t bch  = (l >> 3) & 1;

    float acc[4][8][4];
#pragma unroll
    for (int i = 0; i < 4; i++)
#pragma unroll
        for (int j = 0; j < 8; j++)
#pragma unroll
            for (int q = 0; q < 4; q++) acc[i][j][q] = 0.0f;

    load_chunk(0);
    load_chunk(1);

    for (int c = 0; c < NCH; c++) {
        if (c + 2 < NCH) {
            load_chunk(c + 2);
            asm volatile("cp.async.wait_group 2;" ::: "memory");
        } else if (c + 1 < NCH) {
            asm volatile("cp.async.wait_group 1;" ::: "memory");
        } else {
            asm volatile("cp.async.wait_group 0;" ::: "memory");
        }
        __syncthreads();

        const uint32_t stage = sb + (uint32_t)(c % NSTAGE) * STAGE_BYTES;
#pragma unroll
        for (int s = 0; s < 4; s++) {
            uint32_t ah[4][4];
#pragma unroll
            for (int i = 0; i < 4; i++)
                ldsm4(ah[i], stage + swa(arow + i * 16, s * 2 + ach));
            uint32_t bf[4][4];
#pragma unroll
            for (int p = 0; p < 4; p++)
                ldsm4(bf[p], stage + A_ST + swa(brow + p * 16, s * 2 + bch));
#pragma unroll
            for (int i = 0; i < 4; i++)
#pragma unroll
                for (int j = 0; j < 8; j++) {
                    const int p = j >> 1, hh = (j & 1) * 2;
                    uint32_t h0 = 0u, h1 = 0u;
                    mma16816h(h0, h1, ah[i], bf[p][hh], bf[p][hh + 1]);
                    float2 f0 = __half22float2(*(__half2*)&h0);
                    float2 f1 = __half22float2(*(__half2*)&h1);
                    acc[i][j][0] += f0.x;
                    acc[i][j][1] += f0.y;
                    acc[i][j][2] += f1.x;
                    acc[i][j][3] += f1.y;
                }
        }
        __syncthreads();
    }

    const int rowq = l >> 2, colq = (l & 3) * 2;
#pragma unroll
    for (int j = 0; j < 8; j++) {
        const int ccol = n0 + wn * 64 + j * 8 + colq;
        float b0 = 0.f, b1 = 0.f;
        if (BIAS) { b0 = bias[ccol]; b1 = bias[ccol + 1]; }
#pragma unroll
        for (int i = 0; i < 4; i++) {
            const int r = m0 + wm * 64 + i * 16 + rowq;
            if (OUTH) {
                *(uint32_t*)&Ch[(size_t)r * N + ccol] =
                    pack2(acc[i][j][0], acc[i][j][1]);
                *(uint32_t*)&Ch[(size_t)(r + 8) * N + ccol] =
                    pack2(acc[i][j][2], acc[i][j][3]);
            } else {
                float2 v0 = make_float2(acc[i][j][0] + b0, acc[i][j][1] + b1);
                float2 v1 = make_float2(acc[i][j][2] + b0, acc[i][j][3] + b1);
                *(float2*)&C[(size_t)r * N + ccol]       = v0;
                *(float2*)&C[(size_t)(r + 8) * N + ccol] = v1;
            }
        }
    }
}

// ---------------------------------------------------------------------------
// Tensor-core flash attention (fp16, fp32 softmax), causal. (unchanged)
// CTA = (qtile 128 rows, head, batch), 8 warps (256 thr); warp owns 16 q rows.
// KV tiles of 64 rows, 2-stage cp.async ring.
// smem: Q (16KB) + 2 stages of [K|V] (16KB each) = 48KB.
// ---------------------------------------------------------------------------
#define ATT_SMEM (16384 + 2 * 16384)

__global__ __launch_bounds__(256)
void attn_kernel(const __half* __restrict__ qkvh,
                 __half* __restrict__ yh)
{
    extern __shared__ char smem[];
    const uint32_t sb = smem_u32(smem);
    const int tid = threadIdx.x;
    const int w = tid >> 5, l = tid & 31;
    const int qt = blockIdx.x, h = blockIdx.y, b = blockIdx.z;
    const int q0 = qt * 128;
    const int ktmax = 2 * qt + 1;
    const int tok0 = b * SEQ;
    const int koff = h * HD, qoff = CD + h * HD, voff = 2 * CD + h * HD;

    const int qlr = tid >> 1, qlc = (tid & 1) * 4;
    const int klr = tid >> 2, klc = (tid & 3) * 2;

    auto load_kv = [&](int kt) {
        const int k0 = kt * 64;
        const uint32_t base = sb + 16384 + (uint32_t)(kt & 1) * 16384;
        const size_t rowoff = (size_t)(tok0 + k0 + klr) * NQKV;
        const __half* s0 = qkvh + rowoff + koff + klc * 8;
        const __half* s1 = qkvh + rowoff + voff + klc * 8;
#pragma unroll
        for (int c = 0; c < 2; c++) {
            const uint32_t o = swa(klr, klc + c);
            cp16(base + o,        s0 + c * 8);
            cp16(base + 8192 + o, s1 + c * 8);
        }
        asm volatile("cp.async.commit_group;" ::: "memory");
    };

    {
        const size_t rowoff = (size_t)(tok0 + q0 + qlr) * NQKV;
        const __half* s0 = qkvh + rowoff + qoff + qlc * 8;
#pragma unroll
        for (int c = 0; c < 4; c++)
            cp16(sb + swa(qlr, qlc + c), s0 + c * 8);
    }
    load_kv(0);
    load_kv(1);

    const uint32_t qrow = w * 16 + (l & 15);
    const uint32_t qch  = l >> 4;
    const uint32_t krow = (l & 7) + ((l >> 4) << 3);
    const uint32_t kch  = (l >> 3) & 1;
    const uint32_t vrow = (l & 7) + (((l >> 3) & 1) << 3);
    const uint32_t vch  = l >> 4;

    uint32_t qh[4][4];
    float o[8][4];
#pragma unroll
    for (int j = 0; j < 8; j++)
#pragma unroll
        for (int q = 0; q < 4; q++) o[j][q] = 0.0f;
    float sm0 = -1e30f, sm1 = -1e30f, sl0 = 0.0f, sl1 = 0.0f;

    const int r0 = w * 16 + (l >> 2);
    const int r1 = r0 + 8;
    const float scale = 0.125f;

    for (int kt = 0; kt <= ktmax; kt++) {
        if (kt < ktmax) asm volatile("cp.async.wait_group 1;" ::: "memory");
        else            asm volatile("cp.async.wait_group 0;" ::: "memory");
        __syncthreads();

        if (kt == 0) {
#pragma unroll
            for (int s = 0; s < 4; s++)
                ldsm4(qh[s], sb + swa(qrow, s * 2 + qch));
        }

        const uint32_t stage = sb + 16384 + (uint32_t)(kt & 1) * 16384;

        float sacc[8][4];
#pragma unroll
        for (int j = 0; j < 8; j++)
#pragma unroll
            for (int q = 0; q < 4; q++) sacc[j][q] = 0.0f;

#pragma unroll
        for (int s = 0; s < 4; s++) {
#pragma unroll
            for (int p = 0; p < 4; p++) {
                uint32_t kh[4];
                ldsm4(kh, stage + swa(p * 16 + krow, s * 2 + kch));
#pragma unroll
                for (int jj = 0; jj < 2; jj++)
                    mma16816(sacc[p * 2 + jj], qh[s], kh[jj * 2], kh[jj * 2 + 1]);
            }
        }

        const bool mt = (kt >= 2 * qt);
        const int rel = (kt - 2 * qt) * 64;
        float ml0 = -1e30f, ml1 = -1e30f;
#pragma unroll
        for (int j = 0; j < 8; j++) {
            const int c0 = j * 8 + (l & 3) * 2;
            float v0 = sacc[j][0] * scale, v1 = sacc[j][1] * scale;
            float v2 = sacc[j][2] * scale, v3 = sacc[j][3] * scale;
            if (mt) {
                if (rel + c0     > r0) v0 = -1e30f;
                if (rel + c0 + 1 > r0) v1 = -1e30f;
                if (rel + c0     > r1) v2 = -1e30f;
                if (rel + c0 + 1 > r1) v3 = -1e30f;
            }
            sacc[j][0] = v0; sacc[j][1] = v1; sacc[j][2] = v2; sacc[j][3] = v3;
            ml0 = fmaxf(ml0, fmaxf(v0, v1));
            ml1 = fmaxf(ml1, fmaxf(v2, v3));
        }
        ml0 = fmaxf(ml0, __shfl_xor_sync(0xffffffffu, ml0, 1));
        ml0 = fmaxf(ml0, __shfl_xor_sync(0xffffffffu, ml0, 2));
        ml1 = fmaxf(ml1, __shfl_xor_sync(0xffffffffu, ml1, 1));
        ml1 = fmaxf(ml1, __shfl_xor_sync(0xffffffffu, ml1, 2));
        const float mn0 = fmaxf(sm0, ml0), mn1 = fmaxf(sm1, ml1);
        const float cf0 = __expf(sm0 - mn0), cf1 = __expf(sm1 - mn1);
        sm0 = mn0; sm1 = mn1;

        float rs0 = 0.0f, rs1 = 0.0f;
#pragma unroll
        for (int j = 0; j < 8; j++) {
            sacc[j][0] = __expf(sacc[j][0] - mn0);
            sacc[j][1] = __expf(sacc[j][1] - mn0);
            sacc[j][2] = __expf(sacc[j][2] - mn1);
            sacc[j][3] = __expf(sacc[j][3] - mn1);
            rs0 += sacc[j][0] + sacc[j][1];
            rs1 += sacc[j][2] + sacc[j][3];
        }
        rs0 += __shfl_xor_sync(0xffffffffu, rs0, 1);
        rs0 += __shfl_xor_sync(0xffffffffu, rs0, 2);
        rs1 += __shfl_xor_sync(0xffffffffu, rs1, 1);
        rs1 += __shfl_xor_sync(0xffffffffu, rs1, 2);
        sl0 = sl0 * cf0 + rs0;
        sl1 = sl1 * cf1 + rs1;

#pragma unroll
        for (int j = 0; j < 8; j++) {
            o[j][0] *= cf0; o[j][1] *= cf0;
            o[j][2] *= cf1; o[j][3] *= cf1;
        }

        uint32_t ph[4][4];
#pragma unroll
        for (int t = 0; t < 4; t++) {
            ph[t][0] = pack2(sacc[2 * t][0],     sacc[2 * t][1]);
            ph[t][1] = pack2(sacc[2 * t][2],     sacc[2 * t][3]);
            ph[t][2] = pack2(sacc[2 * t + 1][0], sacc[2 * t + 1][1]);
            ph[t][3] = pack2(sacc[2 * t + 1][2], sacc[2 * t + 1][3]);
        }

#pragma unroll
        for (int t = 0; t < 4; t++) {
#pragma unroll
            for (int p = 0; p < 4; p++) {
                uint32_t vh[4];
                ldsm4t(vh, stage + 8192 + swa(t * 16 + vrow, p * 2 + vch));
#pragma unroll
                for (int jj = 0; jj < 2; jj++)
                    mma16816(o[p * 2 + jj], ph[t], vh[jj * 2], vh[jj * 2 + 1]);
            }
        }

        __syncthreads();
        if (kt + 2 <= ktmax) load_kv(kt + 2);
    }

    const float inv0 = 1.0f / sl0, inv1 = 1.0f / sl1;
    const size_t row0 = (size_t)(tok0 + q0 + r0) * CD + h * HD;
    const size_t row1 = (size_t)(tok0 + q0 + r1) * CD + h * HD;
#pragma unroll
    for (int j = 0; j < 8; j++) {
        const int c0 = j * 8 + (l & 3) * 2;
        *(uint32_t*)&yh[row0 + c0] = pack2(o[j][0] * inv0, o[j][1] * inv0);
        *(uint32_t*)&yh[row1 + c0] = pack2(o[j][2] * inv1, o[j][3] * inv1);
    }
}

// ---------------------------------------------------------------------------
extern "C" void kernel_launch(void* const* d_in, const int* in_sizes, int n_in,
                              void* d_out, int out_size)
{
    const float* x      = (const float*)d_in[0];
    const float* w_attn = (const float*)d_in[1];
    const float* w_proj = (const float*)d_in[2];
    const float* b_proj = (const float*)d_in[3];
    float* out = (float*)d_out;

    __half *xh, *wah, *wph, *qkvh, *yh;
    cudaGetSymbolAddress((void**)&xh,   g_xh);
    cudaGetSymbolAddress((void**)&wah,  g_wah);
    cudaGetSymbolAddress((void**)&wph,  g_wph);
    cudaGetSymbolAddress((void**)&qkvh, g_qkvh);
    cudaGetSymbolAddress((void**)&yh,   g_yh);

    cudaFuncSetAttribute(attn_kernel,
                         cudaFuncAttributeMaxDynamicSharedMemorySize, ATT_SMEM);
    cudaFuncSetAttribute(gemm_f16<false, true>,
                         cudaFuncAttributeMaxDynamicSharedMemorySize, GEMM_SMEM);
    cudaFuncSetAttribute(gemm_f16<true, false>,
                         cudaFuncAttributeMaxDynamicSharedMemorySize, GEMM_SMEM);

    // 0) convert inputs to fp16 (single fused launch)
    const int na = MTOK * CD, nb = NQKV * CD, nc = CD * CD;
    cvt3_f16<<<((na + nb + nc) / 4 + 255) / 256, 256>>>(
        x, xh, na, w_attn, wah, nb, w_proj, wph, nc);

    // 1) QKV projection -> qkv fp16
    gemm_f16<false, true><<<dim3(NQKV / 256, MTOK / 128), 256, GEMM_SMEM>>>(
        xh, wah, nullptr, nullptr, qkvh, MTOK, NQKV, CD);

    // 2) tensor-core causal flash attention -> y fp16
    attn_kernel<<<dim3(SEQ / 128, NH, BATCH), 256, ATT_SMEM>>>(qkvh, yh);

    // 3) output projection: out = y @ w_proj^T + b_proj (fp32 out)
    gemm_f16<true, false><<<dim3(CD / 256, MTOK / 128), 256, GEMM_SMEM>>>(
        yh, wph, b_proj, out, nullptr, MTOK, CD, CD);
}

// round 14
// speedup vs baseline: 1.3330x; 1.3330x over previous
#include <cuda_runtime.h>
#include <cuda_fp16.h>
#include <cstdint>

// Problem constants
#define BATCH 8
#define SEQ   1024
#define CD    1024
#define NH    16
#define HD    64
#define MTOK  (BATCH * SEQ)      // 8192 tokens
#define NQKV  (3 * CD)           // 3072

// Scratch (no allocations allowed -> __device__ globals)
__device__ __half g_xh[MTOK * CD];
__device__ __half g_wah[NQKV * CD];
__device__ __half g_wph[CD * CD];
__device__ __half g_qkvh[MTOK * NQKV];
__device__ __half g_yh[MTOK * CD];

// ---------------------------------------------------------------------------
// PTX helpers (portable sm_80+ tensor path: cp.async + ldmatrix + mma.sync)
// ---------------------------------------------------------------------------
__device__ __forceinline__ uint32_t smem_u32(const void* p) {
    return (uint32_t)__cvta_generic_to_shared(p);
}
__device__ __forceinline__ void cp16(uint32_t dst_smem, const void* src) {
    asm volatile("cp.async.cg.shared.global [%0], [%1], 16;"
                 :: "r"(dst_smem), "l"(__cvta_generic_to_global(src)) : "memory");
}
__device__ __forceinline__ void ldsm4(uint32_t* r, uint32_t addr) {
    asm volatile("ldmatrix.sync.aligned.m8n8.x4.shared.b16 {%0,%1,%2,%3}, [%4];"
                 : "=r"(r[0]), "=r"(r[1]), "=r"(r[2]), "=r"(r[3]) : "r"(addr));
}
__device__ __forceinline__ void ldsm4t(uint32_t* r, uint32_t addr) {
    asm volatile("ldmatrix.sync.aligned.m8n8.x4.trans.shared.b16 {%0,%1,%2,%3}, [%4];"
                 : "=r"(r[0]), "=r"(r[1]), "=r"(r[2]), "=r"(r[3]) : "r"(addr));
}
// fp32-accumulate MMA
__device__ __forceinline__ void mma16816(float* d, const uint32_t* a,
                                         uint32_t b0, uint32_t b1) {
    asm volatile(
        "mma.sync.aligned.m16n8k16.row.col.f32.f16.f16.f32 "
        "{%0,%1,%2,%3}, {%4,%5,%6,%7}, {%8,%9}, {%0,%1,%2,%3};"
        : "+f"(d[0]), "+f"(d[1]), "+f"(d[2]), "+f"(d[3])
        : "r"(a[0]), "r"(a[1]), "r"(a[2]), "r"(a[3]), "r"(b0), "r"(b1));
}
__device__ __forceinline__ uint32_t pack2(float a, float b) {
    __half2 h = __floats2half2_rn(a, b);
    return *(uint32_t*)&h;
}

// 128B-row swizzle: 16B chunk ch (0..7) of row r
__device__ __forceinline__ uint32_t swa(uint32_t r, uint32_t ch) {
    return r * 128u + (((ch) ^ (r & 7u)) << 4);
}

// ---------------------------------------------------------------------------
// fused fp32 -> fp16 convert for 3 tensors in one launch
// ---------------------------------------------------------------------------
__global__ __launch_bounds__(256)
void cvt3_f16(const float* __restrict__ a, __half* __restrict__ ah, int na,
              const float* __restrict__ b, __half* __restrict__ bh, int nb,
              const float* __restrict__ c, __half* __restrict__ ch, int nc)
{
    int i = (blockIdx.x * blockDim.x + threadIdx.x) * 4;
    const float* src;
    __half* dst;
    if (i < na)            { src = a + i;            dst = ah + i; }
    else if (i < na + nb)  { src = b + (i - na);     dst = bh + (i - na); }
    else if (i < na + nb + nc) { src = c + (i - na - nb); dst = ch + (i - na - nb); }
    else return;
    float4 v = *(const float4*)src;
    *(uint32_t*)dst       = pack2(v.x, v.y);
    *(uint32_t*)(dst + 2) = pack2(v.z, v.w);
}

// ---------------------------------------------------------------------------
// fp16 mma.sync GEMM: C[m,n] = sum_k A[m,k] * B[n,k]  (+bias)
// 128x256 CTA tile, 8 warps, each 64x64, BK=64, 3-stage cp.async pipe.
// fp32 accumulate (R11 config — proven at the mma.sync roofline).
// ---------------------------------------------------------------------------
#define A_ST   16384                    // 128 rows x 128B
#define B_ST   32768                    // 256 rows x 128B
#define STAGE_BYTES (A_ST + B_ST)       // 48 KB
#define NSTAGE 3
#define GEMM_SMEM (NSTAGE * STAGE_BYTES)  // 144 KB

template <bool BIAS, bool OUTH>
__global__ __launch_bounds__(256, 1)
void gemm_f16(const __half* __restrict__ A, const __half* __restrict__ B,
              const float* __restrict__ bias, float* __restrict__ C,
              __half* __restrict__ Ch, int M, int N, int K)
{
    extern __shared__ char smem[];
    const uint32_t sb = smem_u32(smem);
    const int tid = threadIdx.x;
    const int wid = tid >> 5, l = tid & 31;
    const int m0 = blockIdx.y * 128, n0 = blockIdx.x * 256;
    const int NCH = K >> 6;            // BK=64

    // loader: A = 128 rows, 2 thr/row (4 cp16 each); B = 256 rows, 1 thr/row
    const int alr = tid >> 1, alc = (tid & 1) * 4;
    const __half* agp = A + (size_t)(m0 + alr) * K + alc * 8;
    const __half* bgp = B + (size_t)(n0 + tid) * K;

    auto load_chunk = [&](int c) {
        const uint32_t stage = sb + (uint32_t)(c % NSTAGE) * STAGE_BYTES;
        const int k0 = c << 6;
#pragma unroll
        for (int ch = 0; ch < 4; ch++)
            cp16(stage + swa(alr, alc + ch), agp + k0 + ch * 8);
#pragma unroll
        for (int ch = 0; ch < 8; ch++)
            cp16(stage + A_ST + swa(tid, ch), bgp + k0 + ch * 8);
        asm volatile("cp.async.commit_group;" ::: "memory");
    };

    // warp tile 64x64: wm in {0,1} (m), wn in {0..3} (n)
    const int wm = wid & 1, wn = wid >> 1;

    const uint32_t arow = wm * 64 + (l & 15);
    const uint32_t ach  = l >> 4;
    const uint32_t brow = wn * 64 + (l & 7) + ((l >> 4) << 3);
    const uint32_t bch  = (l >> 3) & 1;

    float acc[4][8][4];
#pragma unroll
    for (int i = 0; i < 4; i++)
#pragma unroll
        for (int j = 0; j < 8; j++)
#pragma unroll
            for (int q = 0; q < 4; q++) acc[i][j][q] = 0.0f;

    load_chunk(0);
    load_chunk(1);

    for (int c = 0; c < NCH; c++) {
        if (c + 2 < NCH) {
            load_chunk(c + 2);
            asm volatile("cp.async.wait_group 2;" ::: "memory");
        } else if (c + 1 < NCH) {
            asm volatile("cp.async.wait_group 1;" ::: "memory");
        } else {
            asm volatile("cp.async.wait_group 0;" ::: "memory");
        }
        __syncthreads();

        const uint32_t stage = sb + (uint32_t)(c % NSTAGE) * STAGE_BYTES;
#pragma unroll
        for (int s = 0; s < 4; s++) {
            uint32_t ah[4][4];
#pragma unroll
            for (int i = 0; i < 4; i++)
                ldsm4(ah[i], stage + swa(arow + i * 16, s * 2 + ach));
            uint32_t bf[4][4];
#pragma unroll
            for (int p = 0; p < 4; p++)
                ldsm4(bf[p], stage + A_ST + swa(brow + p * 16, s * 2 + bch));
#pragma unroll
            for (int i = 0; i < 4; i++)
#pragma unroll
                for (int j = 0; j < 8; j++) {
                    const int p = j >> 1, hh = (j & 1) * 2;
                    mma16816(acc[i][j], ah[i], bf[p][hh], bf[p][hh + 1]);
                }
        }
        __syncthreads();
    }

    const int rowq = l >> 2, colq = (l & 3) * 2;
#pragma unroll
    for (int j = 0; j < 8; j++) {
        const int ccol = n0 + wn * 64 + j * 8 + colq;
        float b0 = 0.f, b1 = 0.f;
        if (BIAS) { b0 = bias[ccol]; b1 = bias[ccol + 1]; }
#pragma unroll
        for (int i = 0; i < 4; i++) {
            const int r = m0 + wm * 64 + i * 16 + rowq;
            if (OUTH) {
                *(uint32_t*)&Ch[(size_t)r * N + ccol] =
                    pack2(acc[i][j][0], acc[i][j][1]);
                *(uint32_t*)&Ch[(size_t)(r + 8) * N + ccol] =
                    pack2(acc[i][j][2], acc[i][j][3]);
            } else {
                float2 v0 = make_float2(acc[i][j][0] + b0, acc[i][j][1] + b1);
                float2 v1 = make_float2(acc[i][j][2] + b0, acc[i][j][3] + b1);
                *(float2*)&C[(size_t)r * N + ccol]       = v0;
                *(float2*)&C[(size_t)(r + 8) * N + ccol] = v1;
            }
        }
    }
}

// ---------------------------------------------------------------------------
// Tensor-core flash attention (fp16, fp32 softmax), causal.
// CTA = (qtile 128 rows, head, batch), 8 warps (256 thr); warp owns 16 q rows.
// KV tiles of 64 rows, 2-stage cp.async ring.
// NEW: warps 0-3 skip the last diagonal tile entirely (fully masked, exact).
// smem: Q (16KB) + 2 stages of [K|V] (16KB each) = 48KB.
// ---------------------------------------------------------------------------
#define ATT_SMEM (16384 + 2 * 16384)

__global__ __launch_bounds__(256)
void attn_kernel(const __half* __restrict__ qkvh,
                 __half* __restrict__ yh)
{
    extern __shared__ char smem[];
    const uint32_t sb = smem_u32(smem);
    const int tid = threadIdx.x;
    const int w = tid >> 5, l = tid & 31;
    const int qt = blockIdx.x, h = blockIdx.y, b = blockIdx.z;
    const int q0 = qt * 128;
    const int ktmax = 2 * qt + 1;
    const int tok0 = b * SEQ;
    const int koff = h * HD, qoff = CD + h * HD, voff = 2 * CD + h * HD;

    const int qlr = tid >> 1, qlc = (tid & 1) * 4;
    const int klr = tid >> 2, klc = (tid & 3) * 2;

    auto load_kv = [&](int kt) {
        const int k0 = kt * 64;
        const uint32_t base = sb + 16384 + (uint32_t)(kt & 1) * 16384;
        const size_t rowoff = (size_t)(tok0 + k0 + klr) * NQKV;
        const __half* s0 = qkvh + rowoff + koff + klc * 8;
        const __half* s1 = qkvh + rowoff + voff + klc * 8;
#pragma unroll
        for (int c = 0; c < 2; c++) {
            const uint32_t o = swa(klr, klc + c);
            cp16(base + o,        s0 + c * 8);
            cp16(base + 8192 + o, s1 + c * 8);
        }
        asm volatile("cp.async.commit_group;" ::: "memory");
    };

    {
        const size_t rowoff = (size_t)(tok0 + q0 + qlr) * NQKV;
        const __half* s0 = qkvh + rowoff + qoff + qlc * 8;
#pragma unroll
        for (int c = 0; c < 4; c++)
            cp16(sb + swa(qlr, qlc + c), s0 + c * 8);
    }
    load_kv(0);
    load_kv(1);

    const uint32_t qrow = w * 16 + (l & 15);
    const uint32_t qch  = l >> 4;
    const uint32_t krow = (l & 7) + ((l >> 4) << 3);
    const uint32_t kch  = (l >> 3) & 1;
    const uint32_t vrow = (l & 7) + (((l >> 3) & 1) << 3);
    const uint32_t vch  = l >> 4;

    uint32_t qh[4][4];
    float o[8][4];
#pragma unroll
    for (int j = 0; j < 8; j++)
#pragma unroll
        for (int q = 0; q < 4; q++) o[j][q] = 0.0f;
    float sm0 = -1e30f, sm1 = -1e30f, sl0 = 0.0f, sl1 = 0.0f;

    const int r0 = w * 16 + (l >> 2);
    const int r1 = r0 + 8;
    const float scale = 0.125f;

    for (int kt = 0; kt <= ktmax; kt++) {
        if (kt < ktmax) asm volatile("cp.async.wait_group 1;" ::: "memory");
        else            asm volatile("cp.async.wait_group 0;" ::: "memory");
        __syncthreads();

        if (kt == 0) {
#pragma unroll
            for (int s = 0; s < 4; s++)
                ldsm4(qh[s], sb + swa(qrow, s * 2 + qch));
        }

        // Last diagonal tile covers key cols 64..127 (relative); warps 0-3 own
        // q rows 0..63 -> every entry masked. Skipping is exact (P=0, cf=1).
        const bool skip_tile = (kt == ktmax) && (kt == 2 * qt + 1) && (w < 4);

        const uint32_t stage = sb + 16384 + (uint32_t)(kt & 1) * 16384;

        if (!skip_tile) {
            float sacc[8][4];
#pragma unroll
            for (int j = 0; j < 8; j++)
#pragma unroll
                for (int q = 0; q < 4; q++) sacc[j][q] = 0.0f;

#pragma unroll
            for (int s = 0; s < 4; s++) {
#pragma unroll
                for (int p = 0; p < 4; p++) {
                    uint32_t kh[4];
                    ldsm4(kh, stage + swa(p * 16 + krow, s * 2 + kch));
#pragma unroll
                    for (int jj = 0; jj < 2; jj++)
                        mma16816(sacc[p * 2 + jj], qh[s], kh[jj * 2], kh[jj * 2 + 1]);
                }
            }

            const bool mt = (kt >= 2 * qt);
            const int rel = (kt - 2 * qt) * 64;
            float ml0 = -1e30f, ml1 = -1e30f;
#pragma unroll
            for (int j = 0; j < 8; j++) {
                const int c0 = j * 8 + (l & 3) * 2;
                float v0 = sacc[j][0] * scale, v1 = sacc[j][1] * scale;
                float v2 = sacc[j][2] * scale, v3 = sacc[j][3] * scale;
                if (mt) {
                    if (rel + c0     > r0) v0 = -1e30f;
                    if (rel + c0 + 1 > r0) v1 = -1e30f;
                    if (rel + c0     > r1) v2 = -1e30f;
                    if (rel + c0 + 1 > r1) v3 = -1e30f;
                }
                sacc[j][0] = v0; sacc[j][1] = v1; sacc[j][2] = v2; sacc[j][3] = v3;
                ml0 = fmaxf(ml0, fmaxf(v0, v1));
                ml1 = fmaxf(ml1, fmaxf(v2, v3));
            }
            ml0 = fmaxf(ml0, __shfl_xor_sync(0xffffffffu, ml0, 1));
            ml0 = fmaxf(ml0, __shfl_xor_sync(0xffffffffu, ml0, 2));
            ml1 = fmaxf(ml1, __shfl_xor_sync(0xffffffffu, ml1, 1));
            ml1 = fmaxf(ml1, __shfl_xor_sync(0xffffffffu, ml1, 2));
            const float mn0 = fmaxf(sm0, ml0), mn1 = fmaxf(sm1, ml1);
            const float cf0 = __expf(sm0 - mn0), cf1 = __expf(sm1 - mn1);
            sm0 = mn0; sm1 = mn1;

            float rs0 = 0.0f, rs1 = 0.0f;
#pragma unroll
            for (int j = 0; j < 8; j++) {
                sacc[j][0] = __expf(sacc[j][0] - mn0);
                sacc[j][1] = __expf(sacc[j][1] - mn0);
                sacc[j][2] = __expf(sacc[j][2] - mn1);
                sacc[j][3] = __expf(sacc[j][3] - mn1);
                rs0 += sacc[j][0] + sacc[j][1];
                rs1 += sacc[j][2] + sacc[j][3];
            }
            rs0 += __shfl_xor_sync(0xffffffffu, rs0, 1);
            rs0 += __shfl_xor_sync(0xffffffffu, rs0, 2);
            rs1 += __shfl_xor_sync(0xffffffffu, rs1, 1);
            rs1 += __shfl_xor_sync(0xffffffffu, rs1, 2);
            sl0 = sl0 * cf0 + rs0;
            sl1 = sl1 * cf1 + rs1;

#pragma unroll
            for (int j = 0; j < 8; j++) {
                o[j][0] *= cf0; o[j][1] *= cf0;
                o[j][2] *= cf1; o[j][3] *= cf1;
            }

            uint32_t ph[4][4];
#pragma unroll
            for (int t = 0; t < 4; t++) {
                ph[t][0] = pack2(sacc[2 * t][0],     sacc[2 * t][1]);
                ph[t][1] = pack2(sacc[2 * t][2],     sacc[2 * t][3]);
                ph[t][2] = pack2(sacc[2 * t + 1][0], sacc[2 * t + 1][1]);
                ph[t][3] = pack2(sacc[2 * t + 1][2], sacc[2 * t + 1][3]);
            }

#pragma unroll
            for (int t = 0; t < 4; t++) {
#pragma unroll
                for (int p = 0; p < 4; p++) {
                    uint32_t vh[4];
                    ldsm4t(vh, stage + 8192 + swa(t * 16 + vrow, p * 2 + vch));
#pragma unroll
                    for (int jj = 0; jj < 2; jj++)
                        mma16816(o[p * 2 + jj], ph[t], vh[jj * 2], vh[jj * 2 + 1]);
                }
            }
        }

        __syncthreads();
        if (kt + 2 <= ktmax) load_kv(kt + 2);
    }

    const float inv0 = 1.0f / sl0, inv1 = 1.0f / sl1;
    const size_t row0 = (size_t)(tok0 + q0 + r0) * CD + h * HD;
    const size_t row1 = (size_t)(tok0 + q0 + r1) * CD + h * HD;
#pragma unroll
    for (int j = 0; j < 8; j++) {
        const int c0 = j * 8 + (l & 3) * 2;
        *(uint32_t*)&yh[row0 + c0] = pack2(o[j][0] * inv0, o[j][1] * inv0);
        *(uint32_t*)&yh[row1 + c0] = pack2(o[j][2] * inv1, o[j][3] * inv1);
    }
}

// ---------------------------------------------------------------------------
extern "C" void kernel_launch(void* const* d_in, const int* in_sizes, int n_in,
                              void* d_out, int out_size)
{
    const float* x      = (const float*)d_in[0];
    const float* w_attn = (const float*)d_in[1];
    const float* w_proj = (const float*)d_in[2];
    const float* b_proj = (const float*)d_in[3];
    float* out = (float*)d_out;

    __half *xh, *wah, *wph, *qkvh, *yh;
    cudaGetSymbolAddress((void**)&xh,   g_xh);
    cudaGetSymbolAddress((void**)&wah,  g_wah);
    cudaGetSymbolAddress((void**)&wph,  g_wph);
    cudaGetSymbolAddress((void**)&qkvh, g_qkvh);
    cudaGetSymbolAddress((void**)&yh,   g_yh);

    cudaFuncSetAttribute(attn_kernel,
                         cudaFuncAttributeMaxDynamicSharedMemorySize, ATT_SMEM);
    cudaFuncSetAttribute(gemm_f16<false, true>,
                         cudaFuncAttributeMaxDynamicSharedMemorySize, GEMM_SMEM);
    cudaFuncSetAttribute(gemm_f16<true, false>,
                         cudaFuncAttributeMaxDynamicSharedMemorySize, GEMM_SMEM);

    // 0) convert inputs to fp16 (single fused launch)
    const int na = MTOK * CD, nb = NQKV * CD, nc = CD * CD;
    cvt3_f16<<<((na + nb + nc) / 4 + 255) / 256, 256>>>(
        x, xh, na, w_attn, wah, nb, w_proj, wph, nc);

    // 1) QKV projection -> qkv fp16
    gemm_f16<false, true><<<dim3(NQKV / 256, MTOK / 128), 256, GEMM_SMEM>>>(
        xh, wah, nullptr, nullptr, qkvh, MTOK, NQKV, CD);

    // 2) tensor-core causal flash attention -> y fp16
    attn_kernel<<<dim3(SEQ / 128, NH, BATCH), 256, ATT_SMEM>>>(qkvh, yh);

    // 3) output projection: out = y @ w_proj^T + b_proj (fp32 out)
    gemm_f16<true, false><<<dim3(CD / 256, MTOK / 128), 256, GEMM_SMEM>>>(
        yh, wph, b_proj, out, nullptr, MTOK, CD, CD);
}

// round 15
// speedup vs baseline: 1.3522x; 1.0144x over previous
#include <cuda_runtime.h>
#include <cuda_fp16.h>
#include <cstdint>

// Problem constants
#define BATCH 8
#define SEQ   1024
#define CD    1024
#define NH    16
#define HD    64
#define MTOK  (BATCH * SEQ)      // 8192 tokens
#define NQKV  (3 * CD)           // 3072

// Scratch (no allocations allowed -> __device__ globals)
__device__ __half g_xh[MTOK * CD];
__device__ __half g_wah[NQKV * CD];
__device__ __half g_wph[CD * CD];
__device__ __half g_qkvh[MTOK * NQKV];
__device__ __half g_yh[MTOK * CD];

// ---------------------------------------------------------------------------
// PTX helpers (portable sm_80+ tensor path: cp.async + ldmatrix + mma.sync)
// ---------------------------------------------------------------------------
__device__ __forceinline__ uint32_t smem_u32(const void* p) {
    return (uint32_t)__cvta_generic_to_shared(p);
}
__device__ __forceinline__ void cp16(uint32_t dst_smem, const void* src) {
    asm volatile("cp.async.cg.shared.global [%0], [%1], 16;"
                 :: "r"(dst_smem), "l"(__cvta_generic_to_global(src)) : "memory");
}
__device__ __forceinline__ void ldsm4(uint32_t* r, uint32_t addr) {
    asm volatile("ldmatrix.sync.aligned.m8n8.x4.shared.b16 {%0,%1,%2,%3}, [%4];"
                 : "=r"(r[0]), "=r"(r[1]), "=r"(r[2]), "=r"(r[3]) : "r"(addr));
}
__device__ __forceinline__ void ldsm4t(uint32_t* r, uint32_t addr) {
    asm volatile("ldmatrix.sync.aligned.m8n8.x4.trans.shared.b16 {%0,%1,%2,%3}, [%4];"
                 : "=r"(r[0]), "=r"(r[1]), "=r"(r[2]), "=r"(r[3]) : "r"(addr));
}
// fp32-accumulate MMA
__device__ __forceinline__ void mma16816(float* d, const uint32_t* a,
                                         uint32_t b0, uint32_t b1) {
    asm volatile(
        "mma.sync.aligned.m16n8k16.row.col.f32.f16.f16.f32 "
        "{%0,%1,%2,%3}, {%4,%5,%6,%7}, {%8,%9}, {%0,%1,%2,%3};"
        : "+f"(d[0]), "+f"(d[1]), "+f"(d[2]), "+f"(d[3])
        : "r"(a[0]), "r"(a[1]), "r"(a[2]), "r"(a[3]), "r"(b0), "r"(b1));
}
__device__ __forceinline__ uint32_t pack2(float a, float b) {
    __half2 h = __floats2half2_rn(a, b);
    return *(uint32_t*)&h;
}

// 128B-row swizzle: 16B chunk ch (0..7) of row r
__device__ __forceinline__ uint32_t swa(uint32_t r, uint32_t ch) {
    return r * 128u + (((ch) ^ (r & 7u)) << 4);
}

// ---------------------------------------------------------------------------
// fused fp32 -> fp16 convert for 3 tensors in one launch
// ---------------------------------------------------------------------------
__global__ __launch_bounds__(256)
void cvt3_f16(const float* __restrict__ a, __half* __restrict__ ah, int na,
              const float* __restrict__ b, __half* __restrict__ bh, int nb,
              const float* __restrict__ c, __half* __restrict__ ch, int nc)
{
    int i = (blockIdx.x * blockDim.x + threadIdx.x) * 4;
    const float* src;
    __half* dst;
    if (i < na)            { src = a + i;            dst = ah + i; }
    else if (i < na + nb)  { src = b + (i - na);     dst = bh + (i - na); }
    else if (i < na + nb + nc) { src = c + (i - na - nb); dst = ch + (i - na - nb); }
    else return;
    float4 v = *(const float4*)src;
    *(uint32_t*)dst       = pack2(v.x, v.y);
    *(uint32_t*)(dst + 2) = pack2(v.z, v.w);
}

// ---------------------------------------------------------------------------
// fp16 mma.sync GEMM: C[m,n] = sum_k A[m,k] * B[n,k]  (+bias)
// 128x256 CTA tile, 8 warps, each 64x64, BK=128 (two 64-half sub-tiles),
// 2-stage cp.async ring (96 KB/stage). Half the barrier crossings of BK=64.
// ---------------------------------------------------------------------------
#define A_SUB  16384                    // 128 rows x 128B (64 halfs)
#define B_SUB  32768                    // 256 rows x 128B
#define STAGE_BYTES (2 * A_SUB + 2 * B_SUB)   // A0|A1|B0|B1 = 96 KB
#define NSTAGE 2
#define GEMM_SMEM (NSTAGE * STAGE_BYTES)      // 192 KB
#define OFF_A0 0
#define OFF_A1 A_SUB
#define OFF_B0 (2 * A_SUB)
#define OFF_B1 (2 * A_SUB + B_SUB)

template <bool BIAS, bool OUTH>
__global__ __launch_bounds__(256, 1)
void gemm_f16(const __half* __restrict__ A, const __half* __restrict__ B,
              const float* __restrict__ bias, float* __restrict__ C,
              __half* __restrict__ Ch, int M, int N, int K)
{
    extern __shared__ char smem[];
    const uint32_t sb = smem_u32(smem);
    const int tid = threadIdx.x;
    const int wid = tid >> 5, l = tid & 31;
    const int m0 = blockIdx.y * 128, n0 = blockIdx.x * 256;
    const int NCH = K >> 7;            // BK=128

    // loader: A = 128 rows, 2 thr/row (4 cp16 per sub); B = 256 rows, 1 thr/row
    const int alr = tid >> 1, alc = (tid & 1) * 4;
    const __half* agp = A + (size_t)(m0 + alr) * K + alc * 8;
    const __half* bgp = B + (size_t)(n0 + tid) * K;

    auto load_chunk = [&](int c) {
        const uint32_t stage = sb + (uint32_t)(c & 1) * STAGE_BYTES;
        const int k0 = c << 7;
#pragma unroll
        for (int sub = 0; sub < 2; sub++) {
            const int ks = k0 + sub * 64;
#pragma unroll
            for (int ch = 0; ch < 4; ch++)
                cp16(stage + OFF_A0 + sub * A_SUB + swa(alr, alc + ch),
                     agp + ks + ch * 8);
#pragma unroll
            for (int ch = 0; ch < 8; ch++)
                cp16(stage + OFF_B0 + sub * B_SUB + swa(tid, ch),
                     bgp + ks + ch * 8);
        }
        asm volatile("cp.async.commit_group;" ::: "memory");
    };

    // warp tile 64x64: wm in {0,1} (m), wn in {0..3} (n)
    const int wm = wid & 1, wn = wid >> 1;

    const uint32_t arow = wm * 64 + (l & 15);
    const uint32_t ach  = l >> 4;
    const uint32_t brow = wn * 64 + (l & 7) + ((l >> 4) << 3);
    const uint32_t bch  = (l >> 3) & 1;

    float acc[4][8][4];
#pragma unroll
    for (int i = 0; i < 4; i++)
#pragma unroll
        for (int j = 0; j < 8; j++)
#pragma unroll
            for (int q = 0; q < 4; q++) acc[i][j][q] = 0.0f;

    load_chunk(0);

    for (int c = 0; c < NCH; c++) {
        if (c + 1 < NCH) {
            load_chunk(c + 1);
            asm volatile("cp.async.wait_group 1;" ::: "memory");
        } else {
            asm volatile("cp.async.wait_group 0;" ::: "memory");
        }
        __syncthreads();

        const uint32_t stage = sb + (uint32_t)(c & 1) * STAGE_BYTES;
#pragma unroll
        for (int sub = 0; sub < 2; sub++) {
            const uint32_t abase = stage + OFF_A0 + sub * A_SUB;
            const uint32_t bbase = stage + OFF_B0 + sub * B_SUB;
#pragma unroll
            for (int s = 0; s < 4; s++) {
                uint32_t ah[4][4];
#pragma unroll
                for (int i = 0; i < 4; i++)
                    ldsm4(ah[i], abase + swa(arow + i * 16, s * 2 + ach));
                uint32_t bf[4][4];
#pragma unroll
                for (int p = 0; p < 4; p++)
                    ldsm4(bf[p], bbase + swa(brow + p * 16, s * 2 + bch));
#pragma unroll
                for (int i = 0; i < 4; i++)
#pragma unroll
                    for (int j = 0; j < 8; j++) {
                        const int p = j >> 1, hh = (j & 1) * 2;
                        mma16816(acc[i][j], ah[i], bf[p][hh], bf[p][hh + 1]);
                    }
            }
        }
        __syncthreads();
    }

    const int rowq = l >> 2, colq = (l & 3) * 2;
#pragma unroll
    for (int j = 0; j < 8; j++) {
        const int ccol = n0 + wn * 64 + j * 8 + colq;
        float b0 = 0.f, b1 = 0.f;
        if (BIAS) { b0 = bias[ccol]; b1 = bias[ccol + 1]; }
#pragma unroll
        for (int i = 0; i < 4; i++) {
            const int r = m0 + wm * 64 + i * 16 + rowq;
            if (OUTH) {
                *(uint32_t*)&Ch[(size_t)r * N + ccol] =
                    pack2(acc[i][j][0], acc[i][j][1]);
                *(uint32_t*)&Ch[(size_t)(r + 8) * N + ccol] =
                    pack2(acc[i][j][2], acc[i][j][3]);
            } else {
                float2 v0 = make_float2(acc[i][j][0] + b0, acc[i][j][1] + b1);
                float2 v1 = make_float2(acc[i][j][2] + b0, acc[i][j][3] + b1);
                *(float2*)&C[(size_t)r * N + ccol]       = v0;
                *(float2*)&C[(size_t)(r + 8) * N + ccol] = v1;
            }
        }
    }
}

// ---------------------------------------------------------------------------
// Tensor-core flash attention (fp16, fp32 softmax), causal. (R14 config)
// CTA = (qtile 128 rows, head, batch), 8 warps (256 thr); warp owns 16 q rows.
// KV tiles of 64 rows, 2-stage cp.async ring; warps 0-3 skip last diag tile.
// smem: Q (16KB) + 2 stages of [K|V] (16KB each) = 48KB.
// ---------------------------------------------------------------------------
#define ATT_SMEM (16384 + 2 * 16384)

__global__ __launch_bounds__(256)
void attn_kernel(const __half* __restrict__ qkvh,
                 __half* __restrict__ yh)
{
    extern __shared__ char smem[];
    const uint32_t sb = smem_u32(smem);
    const int tid = threadIdx.x;
    const int w = tid >> 5, l = tid & 31;
    const int qt = blockIdx.x, h = blockIdx.y, b = blockIdx.z;
    const int q0 = qt * 128;
    const int ktmax = 2 * qt + 1;
    const int tok0 = b * SEQ;
    const int koff = h * HD, qoff = CD + h * HD, voff = 2 * CD + h * HD;

    const int qlr = tid >> 1, qlc = (tid & 1) * 4;
    const int klr = tid >> 2, klc = (tid & 3) * 2;

    auto load_kv = [&](int kt) {
        const int k0 = kt * 64;
        const uint32_t base = sb + 16384 + (uint32_t)(kt & 1) * 16384;
        const size_t rowoff = (size_t)(tok0 + k0 + klr) * NQKV;
        const __half* s0 = qkvh + rowoff + koff + klc * 8;
        const __half* s1 = qkvh + rowoff + voff + klc * 8;
#pragma unroll
        for (int c = 0; c < 2; c++) {
            const uint32_t o = swa(klr, klc + c);
            cp16(base + o,        s0 + c * 8);
            cp16(base + 8192 + o, s1 + c * 8);
        }
        asm volatile("cp.async.commit_group;" ::: "memory");
    };

    {
        const size_t rowoff = (size_t)(tok0 + q0 + qlr) * NQKV;
        const __half* s0 = qkvh + rowoff + qoff + qlc * 8;
#pragma unroll
        for (int c = 0; c < 4; c++)
            cp16(sb + swa(qlr, qlc + c), s0 + c * 8);
    }
    load_kv(0);
    load_kv(1);

    const uint32_t qrow = w * 16 + (l & 15);
    const uint32_t qch  = l >> 4;
    const uint32_t krow = (l & 7) + ((l >> 4) << 3);
    const uint32_t kch  = (l >> 3) & 1;
    const uint32_t vrow = (l & 7) + (((l >> 3) & 1) << 3);
    const uint32_t vch  = l >> 4;

    uint32_t qh[4][4];
    float o[8][4];
#pragma unroll
    for (int j = 0; j < 8; j++)
#pragma unroll
        for (int q = 0; q < 4; q++) o[j][q] = 0.0f;
    float sm0 = -1e30f, sm1 = -1e30f, sl0 = 0.0f, sl1 = 0.0f;

    const int r0 = w * 16 + (l >> 2);
    const int r1 = r0 + 8;
    const float scale = 0.125f;

    for (int kt = 0; kt <= ktmax; kt++) {
        if (kt < ktmax) asm volatile("cp.async.wait_group 1;" ::: "memory");
        else            asm volatile("cp.async.wait_group 0;" ::: "memory");
        __syncthreads();

        if (kt == 0) {
#pragma unroll
            for (int s = 0; s < 4; s++)
                ldsm4(qh[s], sb + swa(qrow, s * 2 + qch));
        }

        // Last diagonal tile covers key cols 64..127 (relative); warps 0-3 own
        // q rows 0..63 -> every entry masked. Skipping is exact (P=0, cf=1).
        const bool skip_tile = (kt == ktmax) && (kt == 2 * qt + 1) && (w < 4);

        const uint32_t stage = sb + 16384 + (uint32_t)(kt & 1) * 16384;

        if (!skip_tile) {
            float sacc[8][4];
#pragma unroll
            for (int j = 0; j < 8; j++)
#pragma unroll
                for (int q = 0; q < 4; q++) sacc[j][q] = 0.0f;

#pragma unroll
            for (int s = 0; s < 4; s++) {
#pragma unroll
                for (int p = 0; p < 4; p++) {
                    uint32_t kh[4];
                    ldsm4(kh, stage + swa(p * 16 + krow, s * 2 + kch));
#pragma unroll
                    for (int jj = 0; jj < 2; jj++)
                        mma16816(sacc[p * 2 + jj], qh[s], kh[jj * 2], kh[jj * 2 + 1]);
                }
            }

            const bool mt = (kt >= 2 * qt);
            const int rel = (kt - 2 * qt) * 64;
            float ml0 = -1e30f, ml1 = -1e30f;
#pragma unroll
            for (int j = 0; j < 8; j++) {
                const int c0 = j * 8 + (l & 3) * 2;
                float v0 = sacc[j][0] * scale, v1 = sacc[j][1] * scale;
                float v2 = sacc[j][2] * scale, v3 = sacc[j][3] * scale;
                if (mt) {
                    if (rel + c0     > r0) v0 = -1e30f;
                    if (rel + c0 + 1 > r0) v1 = -1e30f;
                    if (rel + c0     > r1) v2 = -1e30f;
                    if (rel + c0 + 1 > r1) v3 = -1e30f;
                }
                sacc[j][0] = v0; sacc[j][1] = v1; sacc[j][2] = v2; sacc[j][3] = v3;
                ml0 = fmaxf(ml0, fmaxf(v0, v1));
                ml1 = fmaxf(ml1, fmaxf(v2, v3));
            }
            ml0 = fmaxf(ml0, __shfl_xor_sync(0xffffffffu, ml0, 1));
            ml0 = fmaxf(ml0, __shfl_xor_sync(0xffffffffu, ml0, 2));
            ml1 = fmaxf(ml1, __shfl_xor_sync(0xffffffffu, ml1, 1));
            ml1 = fmaxf(ml1, __shfl_xor_sync(0xffffffffu, ml1, 2));
            const float mn0 = fmaxf(sm0, ml0), mn1 = fmaxf(sm1, ml1);
            const float cf0 = __expf(sm0 - mn0), cf1 = __expf(sm1 - mn1);
            sm0 = mn0; sm1 = mn1;

            float rs0 = 0.0f, rs1 = 0.0f;
#pragma unroll
            for (int j = 0; j < 8; j++) {
                sacc[j][0] = __expf(sacc[j][0] - mn0);
                sacc[j][1] = __expf(sacc[j][1] - mn0);
                sacc[j][2] = __expf(sacc[j][2] - mn1);
                sacc[j][3] = __expf(sacc[j][3] - mn1);
                rs0 += sacc[j][0] + sacc[j][1];
                rs1 += sacc[j][2] + sacc[j][3];
            }
            rs0 += __shfl_xor_sync(0xffffffffu, rs0, 1);
            rs0 += __shfl_xor_sync(0xffffffffu, rs0, 2);
            rs1 += __shfl_xor_sync(0xffffffffu, rs1, 1);
            rs1 += __shfl_xor_sync(0xffffffffu, rs1, 2);
            sl0 = sl0 * cf0 + rs0;
            sl1 = sl1 * cf1 + rs1;

#pragma unroll
            for (int j = 0; j < 8; j++) {
                o[j][0] *= cf0; o[j][1] *= cf0;
                o[j][2] *= cf1; o[j][3] *= cf1;
            }

            uint32_t ph[4][4];
#pragma unroll
            for (int t = 0; t < 4; t++) {
                ph[t][0] = pack2(sacc[2 * t][0],     sacc[2 * t][1]);
                ph[t][1] = pack2(sacc[2 * t][2],     sacc[2 * t][3]);
                ph[t][2] = pack2(sacc[2 * t + 1][0], sacc[2 * t + 1][1]);
                ph[t][3] = pack2(sacc[2 * t + 1][2], sacc[2 * t + 1][3]);
            }

#pragma unroll
            for (int t = 0; t < 4; t++) {
#pragma unroll
                for (int p = 0; p < 4; p++) {
                    uint32_t vh[4];
                    ldsm4t(vh, stage + 8192 + swa(t * 16 + vrow, p * 2 + vch));
#pragma unroll
                    for (int jj = 0; jj < 2; jj++)
                        mma16816(o[p * 2 + jj], ph[t], vh[jj * 2], vh[jj * 2 + 1]);
                }
            }
        }

        __syncthreads();
        if (kt + 2 <= ktmax) load_kv(kt + 2);
    }

    const float inv0 = 1.0f / sl0, inv1 = 1.0f / sl1;
    const size_t row0 = (size_t)(tok0 + q0 + r0) * CD + h * HD;
    const size_t row1 = (size_t)(tok0 + q0 + r1) * CD + h * HD;
#pragma unroll
    for (int j = 0; j < 8; j++) {
        const int c0 = j * 8 + (l & 3) * 2;
        *(uint32_t*)&yh[row0 + c0] = pack2(o[j][0] * inv0, o[j][1] * inv0);
        *(uint32_t*)&yh[row1 + c0] = pack2(o[j][2] * inv1, o[j][3] * inv1);
    }
}

// ---------------------------------------------------------------------------
extern "C" void kernel_launch(void* const* d_in, const int* in_sizes, int n_in,
                              void* d_out, int out_size)
{
    const float* x      = (const float*)d_in[0];
    const float* w_attn = (const float*)d_in[1];
    const float* w_proj = (const float*)d_in[2];
    const float* b_proj = (const float*)d_in[3];
    float* out = (float*)d_out;

    __half *xh, *wah, *wph, *qkvh, *yh;
    cudaGetSymbolAddress((void**)&xh,   g_xh);
    cudaGetSymbolAddress((void**)&wah,  g_wah);
    cudaGetSymbolAddress((void**)&wph,  g_wph);
    cudaGetSymbolAddress((void**)&qkvh, g_qkvh);
    cudaGetSymbolAddress((void**)&yh,   g_yh);

    cudaFuncSetAttribute(attn_kernel,
                         cudaFuncAttributeMaxDynamicSharedMemorySize, ATT_SMEM);
    cudaFuncSetAttribute(gemm_f16<false, true>,
                         cudaFuncAttributeMaxDynamicSharedMemorySize, GEMM_SMEM);
    cudaFuncSetAttribute(gemm_f16<true, false>,
                         cudaFuncAttributeMaxDynamicSharedMemorySize, GEMM_SMEM);

    // 0) convert inputs to fp16 (single fused launch)
    const int na = MTOK * CD, nb = NQKV * CD, nc = CD * CD;
    cvt3_f16<<<((na + nb + nc) / 4 + 255) / 256, 256>>>(
        x, xh, na, w_attn, wah, nb, w_proj, wph, nc);

    // 1) QKV projection -> qkv fp16
    gemm_f16<false, true><<<dim3(NQKV / 256, MTOK / 128), 256, GEMM_SMEM>>>(
        xh, wah, nullptr, nullptr, qkvh, MTOK, NQKV, CD);

    // 2) tensor-core causal flash attention -> y fp16
    attn_kernel<<<dim3(SEQ / 128, NH, BATCH), 256, ATT_SMEM>>>(qkvh, yh);

    // 3) output projection: out = y @ w_proj^T + b_proj (fp32 out)
    gemm_f16<true, false><<<dim3(CD / 256, MTOK / 128), 256, GEMM_SMEM>>>(
        yh, wph, b_proj, out, nullptr, MTOK, CD, CD);
}

// round 16
// speedup vs baseline: 1.4315x; 1.0587x over previous
#include <cuda_runtime.h>
#include <cuda_fp16.h>
#include <cstdint>

// Problem constants
#define BATCH 8
#define SEQ   1024
#define CD    1024
#define NH    16
#define HD    64
#define MTOK  (BATCH * SEQ)      // 8192 tokens
#define NQKV  (3 * CD)           // 3072

// GEMM1 stream-K partition: 768 tiles of 128x256; 740 full + 28 split 5-way
#define G1_NT      768
#define G1_FULL    740
#define G1_REM     28
#define G1_SEGS    5
#define TILE_ELEMS 32768         // 128*256

// Scratch (no allocations allowed -> __device__ globals)
__device__ __half g_xh[MTOK * CD];
__device__ __half g_wah[NQKV * CD];
__device__ __half g_wph[CD * CD];
__device__ __half g_qkvh[MTOK * NQKV];
__device__ __half g_yh[MTOK * CD];
__device__ float  g_part[G1_SEGS * G1_REM * TILE_ELEMS];   // 17.5 MB fp32 partials

// ---------------------------------------------------------------------------
// PTX helpers (portable sm_80+ tensor path: cp.async + ldmatrix + mma.sync)
// ---------------------------------------------------------------------------
__device__ __forceinline__ uint32_t smem_u32(const void* p) {
    return (uint32_t)__cvta_generic_to_shared(p);
}
__device__ __forceinline__ void cp16(uint32_t dst_smem, const void* src) {
    asm volatile("cp.async.cg.shared.global [%0], [%1], 16;"
                 :: "r"(dst_smem), "l"(__cvta_generic_to_global(src)) : "memory");
}
__device__ __forceinline__ void ldsm4(uint32_t* r, uint32_t addr) {
    asm volatile("ldmatrix.sync.aligned.m8n8.x4.shared.b16 {%0,%1,%2,%3}, [%4];"
                 : "=r"(r[0]), "=r"(r[1]), "=r"(r[2]), "=r"(r[3]) : "r"(addr));
}
__device__ __forceinline__ void ldsm4t(uint32_t* r, uint32_t addr) {
    asm volatile("ldmatrix.sync.aligned.m8n8.x4.trans.shared.b16 {%0,%1,%2,%3}, [%4];"
                 : "=r"(r[0]), "=r"(r[1]), "=r"(r[2]), "=r"(r[3]) : "r"(addr));
}
// fp32-accumulate MMA
__device__ __forceinline__ void mma16816(float* d, const uint32_t* a,
                                         uint32_t b0, uint32_t b1) {
    asm volatile(
        "mma.sync.aligned.m16n8k16.row.col.f32.f16.f16.f32 "
        "{%0,%1,%2,%3}, {%4,%5,%6,%7}, {%8,%9}, {%0,%1,%2,%3};"
        : "+f"(d[0]), "+f"(d[1]), "+f"(d[2]), "+f"(d[3])
        : "r"(a[0]), "r"(a[1]), "r"(a[2]), "r"(a[3]), "r"(b0), "r"(b1));
}
__device__ __forceinline__ uint32_t pack2(float a, float b) {
    __half2 h = __floats2half2_rn(a, b);
    return *(uint32_t*)&h;
}

// 128B-row swizzle: 16B chunk ch (0..7) of row r
__device__ __forceinline__ uint32_t swa(uint32_t r, uint32_t ch) {
    return r * 128u + (((ch) ^ (r & 7u)) << 4);
}

// ---------------------------------------------------------------------------
// fused fp32 -> fp16 convert for 3 tensors in one launch
// ---------------------------------------------------------------------------
__global__ __launch_bounds__(256)
void cvt3_f16(const float* __restrict__ a, __half* __restrict__ ah, int na,
              const float* __restrict__ b, __half* __restrict__ bh, int nb,
              const float* __restrict__ c, __half* __restrict__ ch, int nc)
{
    int i = (blockIdx.x * blockDim.x + threadIdx.x) * 4;
    const float* src;
    __half* dst;
    if (i < na)            { src = a + i;            dst = ah + i; }
    else if (i < na + nb)  { src = b + (i - na);     dst = bh + (i - na); }
    else if (i < na + nb + nc) { src = c + (i - na - nb); dst = ch + (i - na - nb); }
    else return;
    float4 v = *(const float4*)src;
    *(uint32_t*)dst       = pack2(v.x, v.y);
    *(uint32_t*)(dst + 2) = pack2(v.z, v.w);
}

// ---------------------------------------------------------------------------
// Shared GEMM tile config: 128x256 CTA tile, 8 warps of 64x64, BK=128
// (two 64-half sub-tiles per chunk), 2-stage cp.async ring.
// ---------------------------------------------------------------------------
#define A_SUB  16384                    // 128 rows x 128B (64 halfs)
#define B_SUB  32768                    // 256 rows x 128B
#define STAGE_BYTES (2 * A_SUB + 2 * B_SUB)   // A0|A1|B0|B1 = 96 KB
#define GEMM_SMEM (2 * STAGE_BYTES)           // 192 KB
#define OFF_A0 0
#define OFF_B0 (2 * A_SUB)

// ---------------------------------------------------------------------------
// GEMM1 stream-K: qkv = x @ w_attn^T, fp16 out (full tiles) / fp32 partials.
// grid.x = 888: [0,740) full tiles; [740,880) remainder segments; rest idle.
// ---------------------------------------------------------------------------
__global__ __launch_bounds__(256, 1)
void gemm1_sk(const __half* __restrict__ A, const __half* __restrict__ B,
              __half* __restrict__ Ch, float* __restrict__ part)
{
    const int bid = blockIdx.x;
    int tile, c0, c1, seg = 0;
    bool partial;
    if (bid < G1_FULL) {
        tile = bid; c0 = 0; c1 = 8; partial = false;
    } else {
        const int r = bid - G1_FULL;
        if (r >= G1_REM * G1_SEGS) return;
        tile = G1_FULL + r % G1_REM;
        seg  = r / G1_REM;                    // 0..4
        partial = true;
        c0 = (seg < 3) ? 2 * seg : 3 + seg;   // 0,2,4,6,7
        c1 = (seg < 3) ? c0 + 2 : c0 + 1;
    }
    const int m0 = (tile / 12) * 128, n0 = (tile % 12) * 256;
    const int K = CD, N = NQKV;
    const int nch = c1 - c0;

    extern __shared__ char smem[];
    const uint32_t sb = smem_u32(smem);
    const int tid = threadIdx.x;
    const int wid = tid >> 5, l = tid & 31;

    const int alr = tid >> 1, alc = (tid & 1) * 4;
    const __half* agp = A + (size_t)(m0 + alr) * K + alc * 8;
    const __half* bgp = B + (size_t)(n0 + tid) * K;

    auto load_chunk = [&](int i) {
        const uint32_t stage = sb + (uint32_t)(i & 1) * STAGE_BYTES;
        const int k0 = (c0 + i) << 7;
#pragma unroll
        for (int sub = 0; sub < 2; sub++) {
            const int ks = k0 + sub * 64;
#pragma unroll
            for (int ch = 0; ch < 4; ch++)
                cp16(stage + OFF_A0 + sub * A_SUB + swa(alr, alc + ch),
                     agp + ks + ch * 8);
#pragma unroll
            for (int ch = 0; ch < 8; ch++)
                cp16(stage + OFF_B0 + sub * B_SUB + swa(tid, ch),
                     bgp + ks + ch * 8);
        }
        asm volatile("cp.async.commit_group;" ::: "memory");
    };

    const int wm = wid & 1, wn = wid >> 1;
    const uint32_t arow = wm * 64 + (l & 15);
    const uint32_t ach  = l >> 4;
    const uint32_t brow = wn * 64 + (l & 7) + ((l >> 4) << 3);
    const uint32_t bch  = (l >> 3) & 1;

    float acc[4][8][4];
#pragma unroll
    for (int i = 0; i < 4; i++)
#pragma unroll
        for (int j = 0; j < 8; j++)
#pragma unroll
            for (int q = 0; q < 4; q++) acc[i][j][q] = 0.0f;

    load_chunk(0);

    for (int i = 0; i < nch; i++) {
        if (i + 1 < nch) {
            load_chunk(i + 1);
            asm volatile("cp.async.wait_group 1;" ::: "memory");
        } else {
            asm volatile("cp.async.wait_group 0;" ::: "memory");
        }
        __syncthreads();

        const uint32_t stage = sb + (uint32_t)(i & 1) * STAGE_BYTES;
#pragma unroll
        for (int sub = 0; sub < 2; sub++) {
            const uint32_t abase = stage + OFF_A0 + sub * A_SUB;
            const uint32_t bbase = stage + OFF_B0 + sub * B_SUB;
#pragma unroll
            for (int s = 0; s < 4; s++) {
                uint32_t ah[4][4];
#pragma unroll
                for (int ii = 0; ii < 4; ii++)
                    ldsm4(ah[ii], abase + swa(arow + ii * 16, s * 2 + ach));
                uint32_t bf[4][4];
#pragma unroll
                for (int p = 0; p < 4; p++)
                    ldsm4(bf[p], bbase + swa(brow + p * 16, s * 2 + bch));
#pragma unroll
                for (int ii = 0; ii < 4; ii++)
#pragma unroll
                    for (int j = 0; j < 8; j++) {
                        const int p = j >> 1, hh = (j & 1) * 2;
                        mma16816(acc[ii][j], ah[ii], bf[p][hh], bf[p][hh + 1]);
                    }
            }
        }
        __syncthreads();
    }

    const int rowq = l >> 2, colq = (l & 3) * 2;
    if (!partial) {
#pragma unroll
        for (int j = 0; j < 8; j++) {
            const int ccol = n0 + wn * 64 + j * 8 + colq;
#pragma unroll
            for (int i = 0; i < 4; i++) {
                const int r = m0 + wm * 64 + i * 16 + rowq;
                *(uint32_t*)&Ch[(size_t)r * N + ccol] =
                    pack2(acc[i][j][0], acc[i][j][1]);
                *(uint32_t*)&Ch[(size_t)(r + 8) * N + ccol] =
                    pack2(acc[i][j][2], acc[i][j][3]);
            }
        }
    } else {
        float* pp = part + ((size_t)seg * G1_REM + (tile - G1_FULL)) * TILE_ELEMS;
#pragma unroll
        for (int j = 0; j < 8; j++) {
            const int cloc = wn * 64 + j * 8 + colq;
#pragma unroll
            for (int i = 0; i < 4; i++) {
                const int rloc = wm * 64 + i * 16 + rowq;
                *(float2*)&pp[rloc * 256 + cloc] =
                    make_float2(acc[i][j][0], acc[i][j][1]);
                *(float2*)&pp[(rloc + 8) * 256 + cloc] =
                    make_float2(acc[i][j][2], acc[i][j][3]);
            }
        }
    }
}

// Fixup: sum 5 fp32 partials per remainder tile -> fp16 qkv.
__global__ __launch_bounds__(256)
void gemm1_fixup(const float* __restrict__ part, __half* __restrict__ Ch)
{
    const int idx = blockIdx.x * blockDim.x + threadIdx.x;
    const int e2 = idx * 2;
    if (e2 >= G1_REM * TILE_ELEMS) return;
    const int tr = e2 >> 15;          // /32768
    const int el = e2 & (TILE_ELEMS - 1);
    float s0 = 0.0f, s1 = 0.0f;
#pragma unroll
    for (int seg = 0; seg < G1_SEGS; seg++) {
        const float2 v = *(const float2*)&part[((size_t)seg * G1_REM + tr) * TILE_ELEMS + el];
        s0 += v.x; s1 += v.y;
    }
    const int tile = G1_FULL + tr;
    const int m0 = (tile / 12) * 128, n0 = (tile % 12) * 256;
    const int rloc = el >> 8, cloc = el & 255;
    *(uint32_t*)&Ch[(size_t)(m0 + rloc) * NQKV + n0 + cloc] = pack2(s0, s1);
}

// ---------------------------------------------------------------------------
// GEMM2 (uniform): out = y @ w_proj^T + bias, fp32 out. (R15 config)
// ---------------------------------------------------------------------------
__global__ __launch_bounds__(256, 1)
void gemm2_f16(const __half* __restrict__ A, const __half* __restrict__ B,
               const float* __restrict__ bias, float* __restrict__ C,
               int M, int N, int K)
{
    extern __shared__ char smem[];
    const uint32_t sb = smem_u32(smem);
    const int tid = threadIdx.x;
    const int wid = tid >> 5, l = tid & 31;
    const int m0 = blockIdx.y * 128, n0 = blockIdx.x * 256;
    const int NCH = K >> 7;

    const int alr = tid >> 1, alc = (tid & 1) * 4;
    const __half* agp = A + (size_t)(m0 + alr) * K + alc * 8;
    const __half* bgp = B + (size_t)(n0 + tid) * K;

    auto load_chunk = [&](int c) {
        const uint32_t stage = sb + (uint32_t)(c & 1) * STAGE_BYTES;
        const int k0 = c << 7;
#pragma unroll
        for (int sub = 0; sub < 2; sub++) {
            const int ks = k0 + sub * 64;
#pragma unroll
            for (int ch = 0; ch < 4; ch++)
                cp16(stage + OFF_A0 + sub * A_SUB + swa(alr, alc + ch),
                     agp + ks + ch * 8);
#pragma unroll
            for (int ch = 0; ch < 8; ch++)
                cp16(stage + OFF_B0 + sub * B_SUB + swa(tid, ch),
                     bgp + ks + ch * 8);
        }
        asm volatile("cp.async.commit_group;" ::: "memory");
    };

    const int wm = wid & 1, wn = wid >> 1;
    const uint32_t arow = wm * 64 + (l & 15);
    const uint32_t ach  = l >> 4;
    const uint32_t brow = wn * 64 + (l & 7) + ((l >> 4) << 3);
    const uint32_t bch  = (l >> 3) & 1;

    float acc[4][8][4];
#pragma unroll
    for (int i = 0; i < 4; i++)
#pragma unroll
        for (int j = 0; j < 8; j++)
#pragma unroll
            for (int q = 0; q < 4; q++) acc[i][j][q] = 0.0f;

    load_chunk(0);

    for (int c = 0; c < NCH; c++) {
        if (c + 1 < NCH) {
            load_chunk(c + 1);
            asm volatile("cp.async.wait_group 1;" ::: "memory");
        } else {
            asm volatile("cp.async.wait_group 0;" ::: "memory");
        }
        __syncthreads();

        const uint32_t stage = sb + (uint32_t)(c & 1) * STAGE_BYTES;
#pragma unroll
        for (int sub = 0; sub < 2; sub++) {
            const uint32_t abase = stage + OFF_A0 + sub * A_SUB;
            const uint32_t bbase = stage + OFF_B0 + sub * B_SUB;
#pragma unroll
            for (int s = 0; s < 4; s++) {
                uint32_t ah[4][4];
#pragma unroll
                for (int i = 0; i < 4; i++)
                    ldsm4(ah[i], abase + swa(arow + i * 16, s * 2 + ach));
                uint32_t bf[4][4];
#pragma unroll
                for (int p = 0; p < 4; p++)
                    ldsm4(bf[p], bbase + swa(brow + p * 16, s * 2 + bch));
#pragma unroll
                for (int i = 0; i < 4; i++)
#pragma unroll
                    for (int j = 0; j < 8; j++) {
                        const int p = j >> 1, hh = (j & 1) * 2;
                        mma16816(acc[i][j], ah[i], bf[p][hh], bf[p][hh + 1]);
                    }
            }
        }
        __syncthreads();
    }

    const int rowq = l >> 2, colq = (l & 3) * 2;
#pragma unroll
    for (int j = 0; j < 8; j++) {
        const int ccol = n0 + wn * 64 + j * 8 + colq;
        const float b0 = bias[ccol], b1 = bias[ccol + 1];
#pragma unroll
        for (int i = 0; i < 4; i++) {
            const int r = m0 + wm * 64 + i * 16 + rowq;
            *(float2*)&C[(size_t)r * N + ccol] =
                make_float2(acc[i][j][0] + b0, acc[i][j][1] + b1);
            *(float2*)&C[(size_t)(r + 8) * N + ccol] =
                make_float2(acc[i][j][2] + b0, acc[i][j][3] + b1);
        }
    }
}

// ---------------------------------------------------------------------------
// Tensor-core flash attention (fp16, fp32 softmax), causal. (R15 config)
// ---------------------------------------------------------------------------
#define ATT_SMEM (16384 + 2 * 16384)

__global__ __launch_bounds__(256)
void attn_kernel(const __half* __restrict__ qkvh,
                 __half* __restrict__ yh)
{
    extern __shared__ char smem[];
    const uint32_t sb = smem_u32(smem);
    const int tid = threadIdx.x;
    const int w = tid >> 5, l = tid & 31;
    const int qt = blockIdx.x, h = blockIdx.y, b = blockIdx.z;
    const int q0 = qt * 128;
    const int ktmax = 2 * qt + 1;
    const int tok0 = b * SEQ;
    const int koff = h * HD, qoff = CD + h * HD, voff = 2 * CD + h * HD;

    const int qlr = tid >> 1, qlc = (tid & 1) * 4;
    const int klr = tid >> 2, klc = (tid & 3) * 2;

    auto load_kv = [&](int kt) {
        const int k0 = kt * 64;
        const uint32_t base = sb + 16384 + (uint32_t)(kt & 1) * 16384;
        const size_t rowoff = (size_t)(tok0 + k0 + klr) * NQKV;
        const __half* s0 = qkvh + rowoff + koff + klc * 8;
        const __half* s1 = qkvh + rowoff + voff + klc * 8;
#pragma unroll
        for (int c = 0; c < 2; c++) {
            const uint32_t o = swa(klr, klc + c);
            cp16(base + o,        s0 + c * 8);
            cp16(base + 8192 + o, s1 + c * 8);
        }
        asm volatile("cp.async.commit_group;" ::: "memory");
    };

    {
        const size_t rowoff = (size_t)(tok0 + q0 + qlr) * NQKV;
        const __half* s0 = qkvh + rowoff + qoff + qlc * 8;
#pragma unroll
        for (int c = 0; c < 4; c++)
            cp16(sb + swa(qlr, qlc + c), s0 + c * 8);
    }
    load_kv(0);
    load_kv(1);

    const uint32_t qrow = w * 16 + (l & 15);
    const uint32_t qch  = l >> 4;
    const uint32_t krow = (l & 7) + ((l >> 4) << 3);
    const uint32_t kch  = (l >> 3) & 1;
    const uint32_t vrow = (l & 7) + (((l >> 3) & 1) << 3);
    const uint32_t vch  = l >> 4;

    uint32_t qh[4][4];
    float o[8][4];
#pragma unroll
    for (int j = 0; j < 8; j++)
#pragma unroll
        for (int q = 0; q < 4; q++) o[j][q] = 0.0f;
    float sm0 = -1e30f, sm1 = -1e30f, sl0 = 0.0f, sl1 = 0.0f;

    const int r0 = w * 16 + (l >> 2);
    const int r1 = r0 + 8;
    const float scale = 0.125f;

    for (int kt = 0; kt <= ktmax; kt++) {
        if (kt < ktmax) asm volatile("cp.async.wait_group 1;" ::: "memory");
        else            asm volatile("cp.async.wait_group 0;" ::: "memory");
        __syncthreads();

        if (kt == 0) {
#pragma unroll
            for (int s = 0; s < 4; s++)
                ldsm4(qh[s], sb + swa(qrow, s * 2 + qch));
        }

        const bool skip_tile = (kt == ktmax) && (kt == 2 * qt + 1) && (w < 4);
        const uint32_t stage = sb + 16384 + (uint32_t)(kt & 1) * 16384;

        if (!skip_tile) {
            float sacc[8][4];
#pragma unroll
            for (int j = 0; j < 8; j++)
#pragma unroll
                for (int q = 0; q < 4; q++) sacc[j][q] = 0.0f;

#pragma unroll
            for (int s = 0; s < 4; s++) {
#pragma unroll
                for (int p = 0; p < 4; p++) {
                    uint32_t kh[4];
                    ldsm4(kh, stage + swa(p * 16 + krow, s * 2 + kch));
#pragma unroll
                    for (int jj = 0; jj < 2; jj++)
                        mma16816(sacc[p * 2 + jj], qh[s], kh[jj * 2], kh[jj * 2 + 1]);
                }
            }

            const bool mt = (kt >= 2 * qt);
            const int rel = (kt - 2 * qt) * 64;
            float ml0 = -1e30f, ml1 = -1e30f;
#pragma unroll
            for (int j = 0; j < 8; j++) {
                const int c0 = j * 8 + (l & 3) * 2;
                float v0 = sacc[j][0] * scale, v1 = sacc[j][1] * scale;
                float v2 = sacc[j][2] * scale, v3 = sacc[j][3] * scale;
                if (mt) {
                    if (rel + c0     > r0) v0 = -1e30f;
                    if (rel + c0 + 1 > r0) v1 = -1e30f;
                    if (rel + c0     > r1) v2 = -1e30f;
                    if (rel + c0 + 1 > r1) v3 = -1e30f;
                }
                sacc[j][0] = v0; sacc[j][1] = v1; sacc[j][2] = v2; sacc[j][3] = v3;
                ml0 = fmaxf(ml0, fmaxf(v0, v1));
                ml1 = fmaxf(ml1, fmaxf(v2, v3));
            }
            ml0 = fmaxf(ml0, __shfl_xor_sync(0xffffffffu, ml0, 1));
            ml0 = fmaxf(ml0, __shfl_xor_sync(0xffffffffu, ml0, 2));
            ml1 = fmaxf(ml1, __shfl_xor_sync(0xffffffffu, ml1, 1));
            ml1 = fmaxf(ml1, __shfl_xor_sync(0xffffffffu, ml1, 2));
            const float mn0 = fmaxf(sm0, ml0), mn1 = fmaxf(sm1, ml1);
            const float cf0 = __expf(sm0 - mn0), cf1 = __expf(sm1 - mn1);
            sm0 = mn0; sm1 = mn1;

            float rs0 = 0.0f, rs1 = 0.0f;
#pragma unroll
            for (int j = 0; j < 8; j++) {
                sacc[j][0] = __expf(sacc[j][0] - mn0);
                sacc[j][1] = __expf(sacc[j][1] - mn0);
                sacc[j][2] = __expf(sacc[j][2] - mn1);
                sacc[j][3] = __expf(sacc[j][3] - mn1);
                rs0 += sacc[j][0] + sacc[j][1];
                rs1 += sacc[j][2] + sacc[j][3];
            }
            rs0 += __shfl_xor_sync(0xffffffffu, rs0, 1);
            rs0 += __shfl_xor_sync(0xffffffffu, rs0, 2);
            rs1 += __shfl_xor_sync(0xffffffffu, rs1, 1);
            rs1 += __shfl_xor_sync(0xffffffffu, rs1, 2);
            sl0 = sl0 * cf0 + rs0;
            sl1 = sl1 * cf1 + rs1;

#pragma unroll
            for (int j = 0; j < 8; j++) {
                o[j][0] *= cf0; o[j][1] *= cf0;
                o[j][2] *= cf1; o[j][3] *= cf1;
            }

            uint32_t ph[4][4];
#pragma unroll
            for (int t = 0; t < 4; t++) {
                ph[t][0] = pack2(sacc[2 * t][0],     sacc[2 * t][1]);
                ph[t][1] = pack2(sacc[2 * t][2],     sacc[2 * t][3]);
                ph[t][2] = pack2(sacc[2 * t + 1][0], sacc[2 * t + 1][1]);
                ph[t][3] = pack2(sacc[2 * t + 1][2], sacc[2 * t + 1][3]);
            }

#pragma unroll
            for (int t = 0; t < 4; t++) {
#pragma unroll
                for (int p = 0; p < 4; p++) {
                    uint32_t vh[4];
                    ldsm4t(vh, stage + 8192 + swa(t * 16 + vrow, p * 2 + vch));
#pragma unroll
                    for (int jj = 0; jj < 2; jj++)
                        mma16816(o[p * 2 + jj], ph[t], vh[jj * 2], vh[jj * 2 + 1]);
                }
            }
        }

        __syncthreads();
        if (kt + 2 <= ktmax) load_kv(kt + 2);
    }

    const float inv0 = 1.0f / sl0, inv1 = 1.0f / sl1;
    const size_t row0 = (size_t)(tok0 + q0 + r0) * CD + h * HD;
    const size_t row1 = (size_t)(tok0 + q0 + r1) * CD + h * HD;
#pragma unroll
    for (int j = 0; j < 8; j++) {
        const int c0 = j * 8 + (l & 3) * 2;
        *(uint32_t*)&yh[row0 + c0] = pack2(o[j][0] * inv0, o[j][1] * inv0);
        *(uint32_t*)&yh[row1 + c0] = pack2(o[j][2] * inv1, o[j][3] * inv1);
    }
}

// ---------------------------------------------------------------------------
extern "C" void kernel_launch(void* const* d_in, const int* in_sizes, int n_in,
                              void* d_out, int out_size)
{
    const float* x      = (const float*)d_in[0];
    const float* w_attn = (const float*)d_in[1];
    const float* w_proj = (const float*)d_in[2];
    const float* b_proj = (const float*)d_in[3];
    float* out = (float*)d_out;

    __half *xh, *wah, *wph, *qkvh, *yh;
    float* part;
    cudaGetSymbolAddress((void**)&xh,   g_xh);
    cudaGetSymbolAddress((void**)&wah,  g_wah);
    cudaGetSymbolAddress((void**)&wph,  g_wph);
    cudaGetSymbolAddress((void**)&qkvh, g_qkvh);
    cudaGetSymbolAddress((void**)&yh,   g_yh);
    cudaGetSymbolAddress((void**)&part, g_part);

    cudaFuncSetAttribute(attn_kernel,
                         cudaFuncAttributeMaxDynamicSharedMemorySize, ATT_SMEM);
    cudaFuncSetAttribute(gemm1_sk,
                         cudaFuncAttributeMaxDynamicSharedMemorySize, GEMM_SMEM);
    cudaFuncSetAttribute(gemm2_f16,
                         cudaFuncAttributeMaxDynamicSharedMemorySize, GEMM_SMEM);

    // 0) convert inputs to fp16 (single fused launch)
    const int na = MTOK * CD, nb = NQKV * CD, nc = CD * CD;
    cvt3_f16<<<((na + nb + nc) / 4 + 255) / 256, 256>>>(
        x, xh, na, w_attn, wah, nb, w_proj, wph, nc);

    // 1) QKV projection (stream-K): full tiles + remainder split-K + fixup
    gemm1_sk<<<G1_FULL + G1_REM * G1_SEGS + 8, 256, GEMM_SMEM>>>(xh, wah, qkvh, part);
    gemm1_fixup<<<(G1_REM * TILE_ELEMS / 2 + 255) / 256, 256>>>(part, qkvh);

    // 2) tensor-core causal flash attention -> y fp16
    attn_kernel<<<dim3(SEQ / 128, NH, BATCH), 256, ATT_SMEM>>>(qkvh, yh);

    // 3) output projection: out = y @ w_proj^T + b_proj (fp32 out)
    gemm2_f16<<<dim3(CD / 256, MTOK / 128), 256, GEMM_SMEM>>>(
        yh, wph, b_proj, out, MTOK, CD, CD);
}